// round 7
// baseline (speedup 1.0000x reference)
#include <cuda_runtime.h>
#include <math.h>

#define H 768
#define H4 192
#define SEQ 512
#define VOC 30522
#define BATCH 8
#define TMAXX 32
#define EXT (VOC+SEQ)
#define X3H (3*H)
#define X3H4 (X3H/4)
#define NEGV -1e6f
#define D1 (BATCH*TMAXX*EXT)
#define NCTA 148
#define NTHR 512
#define NWARP 16
#define NW (NCTA*NWARP)          /* 2368 warps */
#define GBLK ((VOC+3)/4)         /* 7631 gen blocks of 4 vocab rows */
#define GEN_E 2700
#define GEN_F 5100
#define ZCH 207                  /* vocab chunk per CTA for Z/lp */

// ---------------- persistent device scratch ----------------
__device__ __align__(16) float g_x[BATCH*X3H];     // [ctx | sel | emb]
__device__ __align__(16) float g_th[BATCH*H];
__device__ __align__(16) float g_th2[BATCH*H];
__device__ float g_sc[BATCH*SEQ];
__device__ float g_ws[BATCH*SEQ];
__device__ float g_invden[BATCH];
__device__ float g_css[BATCH*SEQ];
__device__ __align__(16) float g_gRZ[2][BATCH][H];
__device__ __align__(16) float g_gNi[BATCH][H];
__device__ __align__(16) float g_gNh[BATCH][H];
__device__ float g_copyval[BATCH*VOC];
__device__ __align__(16) float g_gen[VOC*8];
__device__ unsigned int       g_amax[BATCH];
__device__ unsigned long long g_amax2[BATCH];
__device__ float g_Zp[NCTA+1][BATCH];
__device__ unsigned char g_present[BATCH*VOC];
__device__ unsigned char g_fo[BATCH*SEQ];

// two-level grid barrier state: 16 arrival counters 1KB apart (distinct LTS
// slices via addr hash bits 10+), plus one release word.
struct PadCnt { unsigned int v; unsigned int pad[255]; };
__device__ PadCnt g_arr[16];
__device__ unsigned int g_rel;

__device__ __forceinline__ unsigned int okey(float f){
    unsigned int u = __float_as_uint(f);
    return (u & 0x80000000u) ? ~u : (u | 0x80000000u);
}
__device__ __forceinline__ float dekey(unsigned int u){
    return (u & 0x80000000u) ? __uint_as_float(u & 0x7FFFFFFFu)
                             : __uint_as_float(~u);
}
__device__ __forceinline__ float wred(float a){
    #pragma unroll
    for (int o = 16; o; o >>= 1) a += __shfl_xor_sync(0xffffffffu, a, o);
    return a;
}
// packed fp32x2 FMA (Blackwell FFMA2 — ptxas never emits this from C++)
__device__ __forceinline__ unsigned long long ffma2(unsigned long long a,
                                                    unsigned long long b,
                                                    unsigned long long c){
    unsigned long long d;
    asm("fma.rn.f32x2 %0, %1, %2, %3;" : "=l"(d) : "l"(a), "l"(b), "l"(c));
    return d;
}
__device__ __forceinline__ float hadd2(unsigned long long a){
    return __uint_as_float((unsigned int)a) + __uint_as_float((unsigned int)(a >> 32));
}
// 768-dot via f32x2: A,B are 16B-aligned
__device__ __forceinline__ float dot768_2(const void* __restrict__ A,
                                          const void* __restrict__ B, int lane){
    const ulonglong2* A2 = (const ulonglong2*)A;
    const ulonglong2* B2 = (const ulonglong2*)B;
    unsigned long long acc = 0ull;
    #pragma unroll
    for (int i = 0; i < 6; i++){
        ulonglong2 x = A2[i*32 + lane], y = B2[i*32 + lane];
        acc = ffma2(x.x, y.x, acc);
        acc = ffma2(x.y, y.y, acc);
    }
    return wred(hadd2(acc));
}
__device__ __forceinline__ float gruc(float rr, float zz, float ni, float nh, float ho){
    float r = 1.f/(1.f + expf(-rr));
    float z = 1.f/(1.f + expf(-zz));
    float n = tanhf(ni + r*nh);
    return (1.f - z)*n + z*ho;
}
// two-level grid barrier: spread arrivals, single master, single release word
__device__ __forceinline__ void gridbar(unsigned int &bep, int cta){
    __syncthreads();
    bep++;
    if (threadIdx.x == 0){
        __threadfence();
        atomicAdd(&g_arr[cta & 15].v, 1u);
        if (cta == 0){
            unsigned int tgt = bep * NCTA;
            for (;;){
                unsigned int s = 0;
                #pragma unroll
                for (int i = 0; i < 16; i++) s += *(volatile unsigned int*)&g_arr[i].v;
                if (s >= tgt) break;
                __nanosleep(64);
            }
            __threadfence();
            atomicExch(&g_rel, bep);
        } else {
            while (*(volatile unsigned int*)&g_rel < bep) __nanosleep(64);
            __threadfence();
        }
    }
    __syncthreads();
}

// ---------------- init ----------------
__global__ void k_init(const int* __restrict__ cls, const float* __restrict__ emb,
                       float* __restrict__ out, int has_tail){
    int i = blockIdx.x*blockDim.x + threadIdx.x;
    int n = gridDim.x*blockDim.x;
    if (i < 16) g_arr[i].v = 0u;
    if (i == 16) g_rel = 0u;
    for (int k = i; k < BATCH*EXT; k += n){
        int b = k/EXT, j = k - b*EXT;
        out[(size_t)b*TMAXX*EXT + j] = (j == 0) ? (float)(*cls) : 0.f;
    }
    const float L = logf(1e-10f);
    for (int k = i; k < BATCH*(TMAXX-1)*SEQ; k += n){
        int b = k/((TMAXX-1)*SEQ);
        int r = k - b*(TMAXX-1)*SEQ;
        int step = r/SEQ + 1;
        int s = r - (step-1)*SEQ;
        out[((size_t)b*TMAXX + step)*EXT + VOC + s] = L;
    }
    for (int k = i; k < BATCH*VOC; k += n) g_present[k] = 0;
    for (int k = i; k < BATCH*H; k += n){
        int b = k/H, j = k - b*H;
        g_x[b*X3H + H   + j] = 0.f;
        g_x[b*X3H + 2*H + j] = emb[H + j];
    }
    if (has_tail && i < BATCH) out[D1 + i*TMAXX] = 1.0f;
}

__global__ void k_prep(const int* __restrict__ inputs){
    int b = blockIdx.x, tid = threadIdx.x;
    __shared__ int ins[SEQ];
    ins[tid] = inputs[b*SEQ + tid];
    __syncthreads();
    int t = ins[tid];
    int fo = (t != 0);
    for (int s = 0; s < tid; s++) if (ins[s] == t) fo = 0;
    g_fo[b*SEQ + tid] = (unsigned char)fo;
    if (fo) g_present[b*VOC + t] = 1;
}

// gen block: 4 vocab rows x 8 batches via f32x2
__device__ __forceinline__ void gen_block(int blk, const float4* __restrict__ ow4,
                                          const float* __restrict__ ob,
                                          const float4* __restrict__ hs4s,
                                          int lane, unsigned int* bmax){
    int v0 = blk*4;
    const ulonglong2* W0 = (const ulonglong2*)(ow4 + (size_t)v0*H4);
    const ulonglong2* W1 = (const ulonglong2*)(ow4 + (size_t)min(v0+1, VOC-1)*H4);
    const ulonglong2* W2 = (const ulonglong2*)(ow4 + (size_t)min(v0+2, VOC-1)*H4);
    const ulonglong2* W3 = (const ulonglong2*)(ow4 + (size_t)min(v0+3, VOC-1)*H4);
    const ulonglong2* HS = (const ulonglong2*)hs4s;
    unsigned long long acc[4][8];
    #pragma unroll
    for (int q = 0; q < 4; q++)
        #pragma unroll
        for (int b2 = 0; b2 < 8; b2++) acc[q][b2] = 0ull;
    #pragma unroll
    for (int i = 0; i < 6; i++){
        ulonglong2 w0 = W0[i*32 + lane], w1 = W1[i*32 + lane];
        ulonglong2 w2 = W2[i*32 + lane], w3 = W3[i*32 + lane];
        #pragma unroll
        for (int b2 = 0; b2 < 8; b2++){
            ulonglong2 h = HS[b2*H4 + i*32 + lane];
            acc[0][b2] = ffma2(w0.x, h.x, acc[0][b2]);
            acc[0][b2] = ffma2(w0.y, h.y, acc[0][b2]);
            acc[1][b2] = ffma2(w1.x, h.x, acc[1][b2]);
            acc[1][b2] = ffma2(w1.y, h.y, acc[1][b2]);
            acc[2][b2] = ffma2(w2.x, h.x, acc[2][b2]);
            acc[2][b2] = ffma2(w2.y, h.y, acc[2][b2]);
            acc[3][b2] = ffma2(w3.x, h.x, acc[3][b2]);
            acc[3][b2] = ffma2(w3.y, h.y, acc[3][b2]);
        }
    }
    #pragma unroll
    for (int vv = 0; vv < 4; vv++){
        float g = 0.f;
        #pragma unroll
        for (int b2 = 0; b2 < 8; b2++){
            float s = wred(hadd2(acc[vv][b2]));
            if (lane == b2) g = s;
        }
        int v = v0 + vv;
        if (lane < 8 && v < VOC){
            g += ob[v];
            if (v == 0) g = NEGV;
            g_gen[(size_t)v*8 + lane] = g;
            atomicMax(&bmax[lane], okey(g));
        }
    }
}

// ---------------- persistent decode loop ----------------
__global__ void __launch_bounds__(NTHR, 1)
k_loop(const float* __restrict__ enc, const int* __restrict__ inputs,
       const float* __restrict__ emb,
       const float4* __restrict__ aw4, const float* __restrict__ ab,
       const float4* __restrict__ cw4, const float* __restrict__ cb,
       const float4* __restrict__ wih4, const float4* __restrict__ whh4,
       const float* __restrict__ bih, const float* __restrict__ bhh,
       const float4* __restrict__ ow4, const float* __restrict__ ob,
       float* __restrict__ out, int has_tail)
{
    const int tid = threadIdx.x, cta = blockIdx.x;
    const int wid = tid >> 5, lane = tid & 31;
    const int W = cta*NWARP + wid;
    unsigned int bep = 0;

    extern __shared__ float smem[];
    float4* xs4 = (float4*)smem;                 // 8*576 float4 = 72 KB (x / th staging)
    float4* hs4 = (float4*)(smem + BATCH*X3H);   // 8*192 float4 = 24 KB (hidden state)

    __shared__ float zred[NWARP][8];
    __shared__ float zinv[8], msh[8];
    __shared__ unsigned long long bkey[8];
    __shared__ unsigned int bmax[8];

    for (int m = tid; m < BATCH*H4; m += NTHR) hs4[m] = make_float4(0.f,0.f,0.f,0.f);
    __syncthreads();

    for (int t = 1; t < TMAXX; t++){
        // ===== A: th = attn_w@h + b  (1536 tasks, f32x2)  || finalize(t-1) (8)
        for (int task = W; task < 1536 + 8; task += NW){
            if (task < 1536){
                int bh = task & 1, j = task >> 1;
                int b0 = bh*4;
                const ulonglong2* r2 = (const ulonglong2*)(aw4 + (size_t)j*H4);
                const ulonglong2* HS = (const ulonglong2*)hs4;
                unsigned long long a0=0ull, a1=0ull, a2=0ull, a3=0ull;
                #pragma unroll
                for (int i = 0; i < 6; i++){
                    ulonglong2 w = r2[i*32 + lane];
                    ulonglong2 h0 = HS[(b0+0)*H4 + i*32 + lane];
                    ulonglong2 h1 = HS[(b0+1)*H4 + i*32 + lane];
                    ulonglong2 h2 = HS[(b0+2)*H4 + i*32 + lane];
                    ulonglong2 h3 = HS[(b0+3)*H4 + i*32 + lane];
                    a0 = ffma2(w.x, h0.x, a0); a0 = ffma2(w.y, h0.y, a0);
                    a1 = ffma2(w.x, h1.x, a1); a1 = ffma2(w.y, h1.y, a1);
                    a2 = ffma2(w.x, h2.x, a2); a2 = ffma2(w.y, h2.y, a2);
                    a3 = ffma2(w.x, h3.x, a3); a3 = ffma2(w.y, h3.y, a3);
                }
                float f0 = wred(hadd2(a0)), f1 = wred(hadd2(a1));
                float f2 = wred(hadd2(a2)), f3 = wred(hadd2(a3));
                if (!lane){
                    float bb = ab[j];
                    g_th[(b0+0)*H + j] = f0 + bb;
                    g_th[(b0+1)*H + j] = f1 + bb;
                    g_th[(b0+2)*H + j] = f2 + bb;
                    g_th[(b0+3)*H + j] = f3 + bb;
                }
            } else if (t > 1){
                int b = task - 1536;
                unsigned long long key = g_amax2[b];
                int samp = 0x7FFFFFFF - (int)(unsigned int)(key & 0xFFFFFFFFull);
                if (!lane && has_tail) out[D1 + b*TMAXX + (t-1)] = (float)samp;
                int kc = (samp > VOC) ? 3 : min(samp, VOC - 1);
                const float4* er = (const float4*)(emb + (size_t)kc*H);
                float4* xd = (float4*)(g_x + b*X3H + 2*H);
                #pragma unroll
                for (int i = 0; i < 6; i++) xd[lane + 32*i] = er[lane + 32*i];
                float ad = 0.f;
                #pragma unroll
                for (int i = 0; i < 16; i++){
                    int s = lane + 32*i;
                    float w = (inputs[b*SEQ + s] == samp) ? g_css[b*SEQ + s] : 0.f;
                    g_ws[b*SEQ + s] = w;
                    ad += fabsf(w);
                }
                ad = wred(ad);
                if (!lane) g_invden[b] = 1.f/fmaxf(ad, 1e-12f);
            }
        }
        gridbar(bep, cta);

        // ===== B: stage th -> smem; attention scores (4096) || selective-read (192)
        {
            const float4* t4g = (const float4*)g_th;
            for (int m = tid; m < BATCH*H4; m += NTHR) xs4[m] = t4g[m];
            __syncthreads();
        }
        for (int task = W; task < 4096 + 192; task += NW){
            if (task < 4096){
                int b = task >> 9, s = task & 511;
                float a = dot768_2(enc + ((size_t)b*SEQ + s)*H, xs4 + b*H4, lane);
                if (!lane) g_sc[b*SEQ + s] = a;
            } else if (t > 1){
                int id = task - 4096;
                int b = id/24, c = id - b*24;
                int h0 = c*32 + lane;
                float inv = g_invden[b];
                const float* ep = enc + (size_t)b*SEQ*H + h0;
                const float* wp = g_ws + b*SEQ;
                float a0=0,a1=0,a2=0,a3=0;
                for (int s = 0; s < SEQ; s += 4){
                    a0 += wp[s+0]*ep[(size_t)(s+0)*H];
                    a1 += wp[s+1]*ep[(size_t)(s+1)*H];
                    a2 += wp[s+2]*ep[(size_t)(s+2)*H];
                    a3 += wp[s+3]*ep[(size_t)(s+3)*H];
                }
                g_x[b*X3H + H + h0] = (a0+a1+a2+a3)*inv;
            }
        }
        gridbar(bep, cta);

        // ===== C: softmax + context (192, 4-way ILP) + resets (1)
        for (int task = W; task < 193; task += NW){
            if (task < 192){
                int b = task/24, c = task - b*24;
                int h0 = c*32 + lane;
                const float* sp = g_sc + b*SEQ;
                float mx = -1e30f;
                #pragma unroll
                for (int i = 0; i < 16; i++) mx = fmaxf(mx, sp[lane + 32*i]);
                #pragma unroll
                for (int o = 16; o; o >>= 1) mx = fmaxf(mx, __shfl_xor_sync(0xffffffffu, mx, o));
                float se = 0.f;
                #pragma unroll
                for (int i = 0; i < 16; i++) se += expf(sp[lane + 32*i] - mx);
                se = wred(se);
                float inv = 1.f/se;
                float a0=0,a1=0,a2=0,a3=0;
                const float* ep = enc + (size_t)b*SEQ*H + h0;
                for (int s0 = 0; s0 < SEQ; s0 += 32){
                    float w = expf(sp[s0 + lane] - mx)*inv;
                    #pragma unroll
                    for (int i = 0; i < 32; i += 4){
                        a0 += __shfl_sync(0xffffffffu, w, i+0)*ep[(size_t)(s0+i+0)*H];
                        a1 += __shfl_sync(0xffffffffu, w, i+1)*ep[(size_t)(s0+i+1)*H];
                        a2 += __shfl_sync(0xffffffffu, w, i+2)*ep[(size_t)(s0+i+2)*H];
                        a3 += __shfl_sync(0xffffffffu, w, i+3)*ep[(size_t)(s0+i+3)*H];
                    }
                }
                g_x[b*X3H + h0] = (a0+a1)+(a2+a3);
            } else {
                if (lane < 8){ g_amax[lane] = 0u; g_amax2[lane] = 0ull; }
            }
        }
        gridbar(bep, cta);

        // ===== D: stage x into smem; GRU (1152 tasks, 2 rows x 8 batches)
        {
            const float4* gx4 = (const float4*)g_x;
            for (int m = tid; m < BATCH*X3H4; m += NTHR) xs4[m] = gx4[m];
            __syncthreads();
            for (int task = W; task < 1152; task += NW){
                int r0 = task*2;
                const float4* wiA = wih4 + (size_t)r0*X3H4;
                const float4* wiB = wiA + X3H4;
                const float4* whA = whh4 + (size_t)r0*H4;
                const float4* whB = whA + H4;
                float giA[8]={0,0,0,0,0,0,0,0}, giB[8]={0,0,0,0,0,0,0,0};
                float ghA[8]={0,0,0,0,0,0,0,0}, ghB[8]={0,0,0,0,0,0,0,0};
                for (int i = 0; i < 18; i++){
                    float4 wa = wiA[i*32 + lane], wb = wiB[i*32 + lane];
                    #pragma unroll
                    for (int b = 0; b < 8; b++){
                        float4 x = xs4[b*X3H4 + i*32 + lane];
                        giA[b] += wa.x*x.x + wa.y*x.y + wa.z*x.z + wa.w*x.w;
                        giB[b] += wb.x*x.x + wb.y*x.y + wb.z*x.z + wb.w*x.w;
                    }
                }
                #pragma unroll
                for (int i = 0; i < 6; i++){
                    float4 wa = whA[i*32 + lane], wb = whB[i*32 + lane];
                    #pragma unroll
                    for (int b = 0; b < 8; b++){
                        float4 h = hs4[b*H4 + i*32 + lane];
                        ghA[b] += wa.x*h.x + wa.y*h.y + wa.z*h.z + wa.w*h.w;
                        ghB[b] += wb.x*h.x + wb.y*h.y + wb.z*h.z + wb.w*h.w;
                    }
                }
                #pragma unroll
                for (int b = 0; b < 8; b++){
                    giA[b] = wred(giA[b]); giB[b] = wred(giB[b]);
                    ghA[b] = wred(ghA[b]); ghB[b] = wred(ghB[b]);
                }
                if (lane < 8){
                    #pragma unroll
                    for (int rr = 0; rr < 2; rr++){
                        int r = r0 + rr;
                        int g = r/H, j = r - g*H;
                        float gi = rr ? giB[0] : giA[0];
                        float gh = rr ? ghB[0] : ghA[0];
                        #pragma unroll
                        for (int b = 1; b < 8; b++){
                            if (lane == b){ gi = rr ? giB[b] : giA[b]; gh = rr ? ghB[b] : ghA[b]; }
                        }
                        float bi = bih[r], bh_ = bhh[r];
                        if (g < 2) g_gRZ[g][lane][j] = gi + gh + bi + bh_;
                        else { g_gNi[lane][j] = gi + bi; g_gNh[lane][j] = gh + bh_; }
                    }
                }
            }
        }
        gridbar(bep, cta);

        // ===== E: combine h locally; th2 (1536, f32x2) + gen [0,GEN_E)
        {
            if (tid < 8) bmax[tid] = 0u;
            for (int m = tid; m < BATCH*H4; m += NTHR){
                int b = m/H4, c = m - b*H4;
                float4 r0 = ((const float4*)g_gRZ[0][b])[c];
                float4 r1 = ((const float4*)g_gRZ[1][b])[c];
                float4 ni = ((const float4*)g_gNi[b])[c];
                float4 nh = ((const float4*)g_gNh[b])[c];
                float4 ho = hs4[m];
                float4 hv;
                hv.x = gruc(r0.x, r1.x, ni.x, nh.x, ho.x);
                hv.y = gruc(r0.y, r1.y, ni.y, nh.y, ho.y);
                hv.z = gruc(r0.z, r1.z, ni.z, nh.z, ho.z);
                hv.w = gruc(r0.w, r1.w, ni.w, nh.w, ho.w);
                hs4[m] = hv;
            }
            __syncthreads();
        }
        for (int task = W; task < 1536 + GEN_E; task += NW){
            if (task < 1536){
                int bh = task & 1, j = task >> 1;
                int b0 = bh*4;
                const ulonglong2* r2 = (const ulonglong2*)(cw4 + (size_t)j*H4);
                const ulonglong2* HS = (const ulonglong2*)hs4;
                unsigned long long a0=0ull, a1=0ull, a2=0ull, a3=0ull;
                #pragma unroll
                for (int i = 0; i < 6; i++){
                    ulonglong2 w = r2[i*32 + lane];
                    ulonglong2 h0 = HS[(b0+0)*H4 + i*32 + lane];
                    ulonglong2 h1 = HS[(b0+1)*H4 + i*32 + lane];
                    ulonglong2 h2 = HS[(b0+2)*H4 + i*32 + lane];
                    ulonglong2 h3 = HS[(b0+3)*H4 + i*32 + lane];
                    a0 = ffma2(w.x, h0.x, a0); a0 = ffma2(w.y, h0.y, a0);
                    a1 = ffma2(w.x, h1.x, a1); a1 = ffma2(w.y, h1.y, a1);
                    a2 = ffma2(w.x, h2.x, a2); a2 = ffma2(w.y, h2.y, a2);
                    a3 = ffma2(w.x, h3.x, a3); a3 = ffma2(w.y, h3.y, a3);
                }
                float f0 = wred(hadd2(a0)), f1 = wred(hadd2(a1));
                float f2 = wred(hadd2(a2)), f3 = wred(hadd2(a3));
                if (!lane){
                    float bb = cb[j];
                    g_th2[(b0+0)*H + j] = f0 + bb;
                    g_th2[(b0+1)*H + j] = f1 + bb;
                    g_th2[(b0+2)*H + j] = f2 + bb;
                    g_th2[(b0+3)*H + j] = f3 + bb;
                }
            } else {
                gen_block(task - 1536, ow4, ob, hs4, lane, bmax);
            }
        }
        gridbar(bep, cta);

        // ===== F: stage th2 -> smem; css (4096) + gen [GEN_E, GEN_F)
        {
            const float4* t4g = (const float4*)g_th2;
            for (int m = tid; m < BATCH*H4; m += NTHR) xs4[m] = t4g[m];
            __syncthreads();
        }
        for (int task = W; task < 4096 + (GEN_F - GEN_E); task += NW){
            if (task < 4096){
                int b = task >> 9, s = task & 511;
                float a = dot768_2(enc + ((size_t)b*SEQ + s)*H, xs4 + b*H4, lane);
                if (!lane) g_css[b*SEQ + s] = a;
            } else {
                gen_block(GEN_E + (task - 4096), ow4, ob, hs4, lane, bmax);
            }
        }
        gridbar(bep, cta);

        // ===== G: copy-chain (128) + gen [GEN_F, GBLK); flush bmax
        for (int task = W; task < 128 + (GBLK - GEN_F); task += NW){
            if (task < 128){
                int b = task >> 4, ch = task & 15;
                int s = ch*32 + lane;
                if (g_fo[b*SEQ + s]){
                    int tok = inputs[b*SEQ + s];
                    const int* ip = inputs + b*SEQ;
                    const float* cp = g_css + b*SEQ;
                    float sum = 0.f;
                    for (int s2 = 0; s2 < SEQ; s2++)
                        if (ip[s2] == tok) sum += cp[s2];
                    g_copyval[b*VOC + tok] = sum;
                    atomicMax(&bmax[b], okey(sum));
                }
            } else {
                gen_block(GEN_F + (task - 128), ow4, ob, hs4, lane, bmax);
            }
        }
        __syncthreads();
        if (tid < 8) atomicMax(&g_amax[tid], bmax[tid]);
        gridbar(bep, cta);

        // ===== H: deterministic Z partials + copy-Z
        {
            float m8[8];
            #pragma unroll
            for (int b = 0; b < 8; b++) m8[b] = dekey(g_amax[b]);
            int v0 = cta*ZCH;
            int cnt = min(ZCH, VOC - v0);
            float e[8] = {0,0,0,0,0,0,0,0};
            if (tid < cnt){
                int v = v0 + tid;
                float4 a = ((const float4*)g_gen)[(size_t)v*2];
                float4 c = ((const float4*)g_gen)[(size_t)v*2 + 1];
                e[0] = __expf(a.x - m8[0]); e[1] = __expf(a.y - m8[1]);
                e[2] = __expf(a.z - m8[2]); e[3] = __expf(a.w - m8[3]);
                e[4] = __expf(c.x - m8[4]); e[5] = __expf(c.y - m8[5]);
                e[6] = __expf(c.z - m8[6]); e[7] = __expf(c.w - m8[7]);
            }
            #pragma unroll
            for (int o = 16; o; o >>= 1){
                #pragma unroll
                for (int b = 0; b < 8; b++) e[b] += __shfl_xor_sync(0xffffffffu, e[b], o);
            }
            if (!lane){
                #pragma unroll
                for (int b = 0; b < 8; b++) zred[wid][b] = e[b];
            }
            __syncthreads();
            if (wid < 8){
                float v = (lane < NWARP) ? zred[lane][wid] : 0.f;
                v = wred(v);
                if (!lane) g_Zp[cta][wid] = v;
            }
            if (cta == NCTA - 1 && wid >= 8){
                int b = wid - 8;
                float e2 = 0.f;
                for (int s = lane; s < SEQ; s += 32)
                    if (g_fo[b*SEQ + s])
                        e2 += __expf(g_copyval[b*VOC + inputs[b*SEQ + s]] - m8[b]);
                e2 = wred(e2);
                if (!lane) g_Zp[NCTA][b] = e2;
            }
        }
        gridbar(bep, cta);

        // ===== I: log-prob row + argmax
        {
            if (tid < 8){ msh[tid] = dekey(g_amax[tid]); bkey[tid] = 0ull; }
            if (wid < 8){
                float z = 0.f;
                for (int i = lane; i <= NCTA; i += 32) z += g_Zp[i][wid];
                z = wred(z);
                if (!lane) zinv[wid] = 1.f/z;
            }
            __syncthreads();
            int v0 = cta*ZCH;
            int cnt = min(ZCH, VOC - v0);
            if (tid < cnt){
                int v = v0 + tid;
                float4 a = ((const float4*)g_gen)[(size_t)v*2];
                float4 c = ((const float4*)g_gen)[(size_t)v*2 + 1];
                float gv[8] = {a.x, a.y, a.z, a.w, c.x, c.y, c.z, c.w};
                unsigned int vk = (unsigned int)(0x7FFFFFFF - v);
                #pragma unroll
                for (int b = 0; b < 8; b++){
                    float p = __expf(gv[b] - msh[b])*zinv[b];
                    if (g_present[b*VOC + v])
                        p += __expf(g_copyval[b*VOC + v] - msh[b])*zinv[b];
                    float lp = __logf(p + 1e-10f);
                    out[((size_t)b*TMAXX + t)*EXT + v] = lp;
                    unsigned long long key = (((unsigned long long)okey(lp)) << 32) | vk;
                    atomicMax(&bkey[b], key);
                }
            }
            __syncthreads();
            if (tid < 8) atomicMax(&g_amax2[tid], bkey[tid]);
        }
        gridbar(bep, cta);
    }

    if (cta == 0 && tid < 8 && has_tail){
        unsigned long long key = g_amax2[tid];
        int samp = 0x7FFFFFFF - (int)(unsigned int)(key & 0xFFFFFFFFull);
        out[D1 + tid*TMAXX + (TMAXX - 1)] = (float)samp;
    }
}

// ---------------- host ----------------
extern "C" void kernel_launch(void* const* d_in, const int* in_sizes, int n_in,
                              void* d_out, int out_size){
    const float* enc    = (const float*)d_in[0];
    const int*   inputs = (const int*)  d_in[1];
    const int*   cls    = (const int*)  d_in[2];
    /* d_in[3] sep_to unused */
    const float* emb    = (const float*)d_in[4];
    const float* aw     = (const float*)d_in[5];
    const float* ab     = (const float*)d_in[6];
    const float* cw     = (const float*)d_in[7];
    const float* cb     = (const float*)d_in[8];
    const float* wih    = (const float*)d_in[9];
    const float* whh    = (const float*)d_in[10];
    const float* bih    = (const float*)d_in[11];
    const float* bhh    = (const float*)d_in[12];
    const float* ow     = (const float*)d_in[13];
    const float* ob     = (const float*)d_in[14];
    float* out = (float*)d_out;
    int has_tail = (out_size >= D1 + BATCH*TMAXX) ? 1 : 0;

    const int smemsz = (BATCH*X3H + BATCH*H)*sizeof(float);   // 96 KB
    cudaFuncSetAttribute(k_loop, cudaFuncAttributeMaxDynamicSharedMemorySize, smemsz);

    k_init<<<512, 256>>>(cls, emb, out, has_tail);
    k_prep<<<BATCH, SEQ>>>(inputs);
    k_loop<<<NCTA, NTHR, smemsz>>>(enc, inputs, emb,
                                   (const float4*)aw, ab,
                                   (const float4*)cw, cb,
                                   (const float4*)wih, (const float4*)whh,
                                   bih, bhh,
                                   (const float4*)ow, ob,
                                   out, has_tail);
}

// round 8
// speedup vs baseline: 1.4156x; 1.4156x over previous
#include <cuda_runtime.h>
#include <math.h>

#define H 768
#define H4 192
#define SEQ 512
#define VOC 30522
#define BATCH 8
#define TMAXX 32
#define EXT (VOC+SEQ)
#define X3H (3*H)
#define X3H4 (X3H/4)
#define NEGV -1e6f
#define D1 (BATCH*TMAXX*EXT)
#define NCTA 148
#define NTHR 512
#define NWARP 16
#define NW (NCTA*NWARP)          /* 2368 warps */
#define GBLK3 (VOC/3)            /* 10174 gen blocks of 3 vocab rows (exact) */
#define G_P4 1664                /* gen blocks in P4: 1536+1536+1664 = 4736 = 2 waves */
#define G_P5 7744                /* gen blocks in P5: 4096+7744 = 11840 = 5 waves */
#define G_P6 (GBLK3 - G_P4 - G_P5)  /* 766; P6 = 128+766 = 894 = 1 wave */
#define ZCH 207                  /* vocab chunk per CTA for Z/lp */

// ---------------- persistent device scratch ----------------
__device__ __align__(16) float g_x[BATCH*X3H];     // [ctx | sel | emb]
__device__ __align__(16) float g_th[BATCH*H];
__device__ __align__(16) float g_th2[BATCH*H];
__device__ float g_sc[BATCH*SEQ];
__device__ float g_ws[BATCH*SEQ];
__device__ float g_invden[BATCH];
__device__ float g_css[BATCH*SEQ];
__device__ __align__(16) float g_selp[4][BATCH*H];  // selective-read partials
__device__ __align__(16) float g_ghv[3][BATCH][H];  // gh + bhh per gate
__device__ __align__(16) float g_gRZ[2][BATCH][H];
__device__ __align__(16) float g_gNi[BATCH][H];
__device__ float g_copyval[BATCH*VOC];
__device__ __align__(16) float g_gen[VOC*8];
__device__ unsigned int       g_amax[BATCH];
__device__ unsigned long long g_amax2[BATCH];
__device__ float g_Zp[NCTA+1][BATCH];
__device__ unsigned char g_present[BATCH*VOC];
__device__ unsigned char g_fo[BATCH*SEQ];
__device__ unsigned int g_bar;

__device__ __forceinline__ unsigned int okey(float f){
    unsigned int u = __float_as_uint(f);
    return (u & 0x80000000u) ? ~u : (u | 0x80000000u);
}
__device__ __forceinline__ float dekey(unsigned int u){
    return (u & 0x80000000u) ? __uint_as_float(u & 0x7FFFFFFFu)
                             : __uint_as_float(~u);
}
__device__ __forceinline__ float wred(float a){
    #pragma unroll
    for (int o = 16; o; o >>= 1) a += __shfl_xor_sync(0xffffffffu, a, o);
    return a;
}
__device__ __forceinline__ unsigned long long ffma2(unsigned long long a,
                                                    unsigned long long b,
                                                    unsigned long long c){
    unsigned long long d;
    asm("fma.rn.f32x2 %0, %1, %2, %3;" : "=l"(d) : "l"(a), "l"(b), "l"(c));
    return d;
}
__device__ __forceinline__ float hadd2(unsigned long long a){
    return __uint_as_float((unsigned int)a) + __uint_as_float((unsigned int)(a >> 32));
}
__device__ __forceinline__ float dot768_2(const void* __restrict__ A,
                                          const void* __restrict__ B, int lane){
    const ulonglong2* A2 = (const ulonglong2*)A;
    const ulonglong2* B2 = (const ulonglong2*)B;
    unsigned long long acc = 0ull;
    #pragma unroll
    for (int i = 0; i < 6; i++){
        ulonglong2 x = A2[i*32 + lane], y = B2[i*32 + lane];
        acc = ffma2(x.x, y.x, acc);
        acc = ffma2(x.y, y.y, acc);
    }
    return wred(hadd2(acc));
}
__device__ __forceinline__ float gruc(float rr, float zz, float ni, float nh, float ho){
    float r = 1.f/(1.f + expf(-rr));
    float z = 1.f/(1.f + expf(-zz));
    float n = tanhf(ni + r*nh);
    return (1.f - z)*n + z*ho;
}
// simple grid barrier (R5 variant — measured best): single counter, leader fence
__device__ __forceinline__ void gridbar(unsigned int &target){
    __syncthreads();
    target += NCTA;
    if (threadIdx.x == 0){
        __threadfence();
        atomicAdd(&g_bar, 1u);
        while (*(volatile unsigned int*)&g_bar < target) __nanosleep(32);
        __threadfence();
    }
    __syncthreads();
}

// ---------------- init (+ prep merged): exactly 2 kernels per launch ----------------
__global__ void k_init(const int* __restrict__ cls, const float* __restrict__ emb,
                       const float* __restrict__ ab, const int* __restrict__ inputs,
                       float* __restrict__ out, int has_tail){
    int i = blockIdx.x*blockDim.x + threadIdx.x;
    int n = gridDim.x*blockDim.x;
    if (i == 0) g_bar = 0u;
    for (int k = i; k < BATCH*EXT; k += n){
        int b = k/EXT, j = k - b*EXT;
        out[(size_t)b*TMAXX*EXT + j] = (j == 0) ? (float)(*cls) : 0.f;
    }
    const float L = logf(1e-10f);
    for (int k = i; k < BATCH*(TMAXX-1)*SEQ; k += n){
        int b = k/((TMAXX-1)*SEQ);
        int r = k - b*(TMAXX-1)*SEQ;
        int step = r/SEQ + 1;
        int s = r - (step-1)*SEQ;
        out[((size_t)b*TMAXX + step)*EXT + VOC + s] = L;
    }
    for (int k = i; k < BATCH*VOC; k += n) g_present[k] = 0;
    for (int k = i; k < 4*BATCH*H; k += n) g_selp[0][k] = 0.f;   // flat over [4][BH]
    for (int k = i; k < BATCH*H; k += n){
        int b = k/H, j = k - b*H;
        g_x[b*X3H + H   + j] = 0.f;
        g_x[b*X3H + 2*H + j] = emb[H + j];
        g_th[k] = ab[j];                     // th for t=1: h0=0 -> th = bias
    }
    if (i < BATCH) g_invden[i] = 1.f;
    if (has_tail && i < BATCH) out[D1 + i*TMAXX] = 1.0f;
    // prep: first-occurrence + present
    if (i < BATCH*SEQ){
        int b = i/SEQ, s = i - b*SEQ;
        const int* ip = inputs + b*SEQ;
        int t = ip[s];
        int fo = (t != 0);
        for (int s2 = 0; s2 < s; s2++) if (ip[s2] == t) fo = 0;
        g_fo[i] = (unsigned char)fo;
        if (fo) g_present[b*VOC + t] = 1;
    }
}

// gen block: 3 vocab rows x 8 batches via f32x2 (VOC = 3*10174 exactly)
__device__ __forceinline__ void gen_block3(int blk, const float4* __restrict__ ow4,
                                           const float* __restrict__ ob,
                                           const float4* __restrict__ hs4s,
                                           int lane, unsigned int* bmax){
    int v0 = blk*3;
    const ulonglong2* W0 = (const ulonglong2*)(ow4 + (size_t)(v0+0)*H4);
    const ulonglong2* W1 = (const ulonglong2*)(ow4 + (size_t)(v0+1)*H4);
    const ulonglong2* W2 = (const ulonglong2*)(ow4 + (size_t)(v0+2)*H4);
    const ulonglong2* HS = (const ulonglong2*)hs4s;
    unsigned long long a0[8], a1[8], a2[8];
    #pragma unroll
    for (int b2 = 0; b2 < 8; b2++){ a0[b2]=0ull; a1[b2]=0ull; a2[b2]=0ull; }
    #pragma unroll
    for (int i = 0; i < 6; i++){
        ulonglong2 w0 = W0[i*32 + lane], w1 = W1[i*32 + lane], w2 = W2[i*32 + lane];
        #pragma unroll
        for (int b2 = 0; b2 < 8; b2++){
            ulonglong2 h = HS[b2*H4 + i*32 + lane];
            a0[b2] = ffma2(w0.x, h.x, a0[b2]); a0[b2] = ffma2(w0.y, h.y, a0[b2]);
            a1[b2] = ffma2(w1.x, h.x, a1[b2]); a1[b2] = ffma2(w1.y, h.y, a1[b2]);
            a2[b2] = ffma2(w2.x, h.x, a2[b2]); a2[b2] = ffma2(w2.y, h.y, a2[b2]);
        }
    }
    #pragma unroll
    for (int vv = 0; vv < 3; vv++){
        float g = 0.f;
        #pragma unroll
        for (int b2 = 0; b2 < 8; b2++){
            unsigned long long av = (vv==0) ? a0[b2] : (vv==1) ? a1[b2] : a2[b2];
            float s = wred(hadd2(av));
            if (lane == b2) g = s;
        }
        int v = v0 + vv;
        if (lane < 8){
            g += ob[v];
            if (v == 0) g = NEGV;
            g_gen[(size_t)v*8 + lane] = g;
            atomicMax(&bmax[lane], okey(g));
        }
    }
}

// ---------------- persistent decode loop ----------------
__global__ void __launch_bounds__(NTHR, 1)
k_loop(const float* __restrict__ enc, const int* __restrict__ inputs,
       const float* __restrict__ emb,
       const float4* __restrict__ aw4, const float* __restrict__ ab,
       const float4* __restrict__ cw4, const float* __restrict__ cb,
       const float4* __restrict__ wih4, const float4* __restrict__ whh4,
       const float* __restrict__ bih, const float* __restrict__ bhh,
       const float4* __restrict__ ow4, const float* __restrict__ ob,
       float* __restrict__ out, int has_tail)
{
    const int tid = threadIdx.x, cta = blockIdx.x;
    const int wid = tid >> 5, lane = tid & 31;
    const int W = cta*NWARP + wid;
    unsigned int bt = 0;

    extern __shared__ float smem[];
    float4* xs4 = (float4*)smem;                 // staging: th / x / th2 (72 KB)
    float4* hs4 = (float4*)(smem + BATCH*X3H);   // hidden state (24 KB)

    __shared__ float zred[NWARP][8];
    __shared__ float zinv[8], msh[8];
    __shared__ unsigned long long bkey[8];
    __shared__ unsigned int bmax[8];

    for (int m = tid; m < BATCH*H4; m += NTHR) hs4[m] = make_float4(0.f,0.f,0.f,0.f);
    __syncthreads();

    for (int t = 1; t < TMAXX; t++){
        // ===== P1: stage th; attention scores (4096) || finalize(t-1) (8)
        {
            const float4* t4g = (const float4*)g_th;
            for (int m = tid; m < BATCH*H4; m += NTHR) xs4[m] = t4g[m];
            __syncthreads();
        }
        for (int task = W; task < 4096 + 8; task += NW){
            if (task < 4096){
                int b = task >> 9, s = task & 511;
                float a = dot768_2(enc + ((size_t)b*SEQ + s)*H, xs4 + b*H4, lane);
                if (!lane) g_sc[b*SEQ + s] = a;
            } else if (t > 1){
                int b = task - 4096;
                unsigned long long key = g_amax2[b];
                int samp = 0x7FFFFFFF - (int)(unsigned int)(key & 0xFFFFFFFFull);
                if (!lane && has_tail) out[D1 + b*TMAXX + (t-1)] = (float)samp;
                int kc = (samp > VOC) ? 3 : min(samp, VOC - 1);
                const float4* er = (const float4*)(emb + (size_t)kc*H);
                float4* xd = (float4*)(g_x + b*X3H + 2*H);
                #pragma unroll
                for (int i = 0; i < 6; i++) xd[lane + 32*i] = er[lane + 32*i];
                float ad = 0.f;
                #pragma unroll
                for (int i = 0; i < 16; i++){
                    int s = lane + 32*i;
                    float w = (inputs[b*SEQ + s] == samp) ? g_css[b*SEQ + s] : 0.f;
                    g_ws[b*SEQ + s] = w;
                    ad += fabsf(w);
                }
                ad = wred(ad);
                if (!lane) g_invden[b] = 1.f/fmaxf(ad, 1e-12f);
            }
        }
        gridbar(bt);

        // ===== P2: sel-read chunks (768) + softmax/context (192) + gh GRU (1152) + reset (1)
        for (int task = W; task < 2113; task += NW){
            if (task < 768){
                if (t > 1){
                    int b = task/96, r = task - b*96;
                    int hc = r >> 2, c4 = r & 3;
                    int h0 = hc*32 + lane, s0 = c4*128;
                    const float* ep = enc + ((size_t)b*SEQ + s0)*H + h0;
                    const float* wp = g_ws + b*SEQ + s0;
                    float a0=0,a1=0,a2=0,a3=0;
                    for (int s = 0; s < 128; s += 4){
                        a0 += wp[s+0]*ep[(size_t)(s+0)*H];
                        a1 += wp[s+1]*ep[(size_t)(s+1)*H];
                        a2 += wp[s+2]*ep[(size_t)(s+2)*H];
                        a3 += wp[s+3]*ep[(size_t)(s+3)*H];
                    }
                    g_selp[c4][b*H + h0] = (a0+a1)+(a2+a3);
                }
            } else if (task < 960){
                int id = task - 768;
                int b = id/24, c = id - b*24;
                int h0 = c*32 + lane;
                const float* sp = g_sc + b*SEQ;
                float mx = -1e30f;
                #pragma unroll
                for (int i = 0; i < 16; i++) mx = fmaxf(mx, sp[lane + 32*i]);
                #pragma unroll
                for (int o = 16; o; o >>= 1) mx = fmaxf(mx, __shfl_xor_sync(0xffffffffu, mx, o));
                float se = 0.f;
                #pragma unroll
                for (int i = 0; i < 16; i++) se += expf(sp[lane + 32*i] - mx);
                se = wred(se);
                float inv = 1.f/se;
                float a0=0,a1=0,a2=0,a3=0;
                const float* ep = enc + (size_t)b*SEQ*H + h0;
                for (int s0 = 0; s0 < SEQ; s0 += 32){
                    float w = expf(sp[s0 + lane] - mx)*inv;
                    #pragma unroll
                    for (int i = 0; i < 32; i += 4){
                        a0 += __shfl_sync(0xffffffffu, w, i+0)*ep[(size_t)(s0+i+0)*H];
                        a1 += __shfl_sync(0xffffffffu, w, i+1)*ep[(size_t)(s0+i+1)*H];
                        a2 += __shfl_sync(0xffffffffu, w, i+2)*ep[(size_t)(s0+i+2)*H];
                        a3 += __shfl_sync(0xffffffffu, w, i+3)*ep[(size_t)(s0+i+3)*H];
                    }
                }
                g_x[b*X3H + h0] = (a0+a1)+(a2+a3);
            } else if (task < 2112){
                int r0 = (task - 960)*2;
                const float4* whA = whh4 + (size_t)r0*H4;
                const float4* whB = whA + H4;
                float ghA[8]={0,0,0,0,0,0,0,0}, ghB[8]={0,0,0,0,0,0,0,0};
                #pragma unroll
                for (int i = 0; i < 6; i++){
                    float4 wa = whA[i*32 + lane], wb = whB[i*32 + lane];
                    #pragma unroll
                    for (int b = 0; b < 8; b++){
                        float4 h = hs4[b*H4 + i*32 + lane];
                        ghA[b] += wa.x*h.x + wa.y*h.y + wa.z*h.z + wa.w*h.w;
                        ghB[b] += wb.x*h.x + wb.y*h.y + wb.z*h.z + wb.w*h.w;
                    }
                }
                #pragma unroll
                for (int b = 0; b < 8; b++){ ghA[b] = wred(ghA[b]); ghB[b] = wred(ghB[b]); }
                if (lane < 8){
                    #pragma unroll
                    for (int rr = 0; rr < 2; rr++){
                        int r = r0 + rr;
                        int g = r/H, j = r - g*H;
                        float gh = rr ? ghB[0] : ghA[0];
                        #pragma unroll
                        for (int b = 1; b < 8; b++)
                            if (lane == b) gh = rr ? ghB[b] : ghA[b];
                        g_ghv[g][lane][j] = gh + bhh[r];
                    }
                }
            } else {
                if (lane < 8){ g_amax[lane] = 0u; g_amax2[lane] = 0ull; }
            }
        }
        gridbar(bt);

        // ===== P3: stage x (ctx|sel-combine|emb) into smem; gi GRU (1152)
        {
            const float4* gx4 = (const float4*)g_x;
            for (int m = tid; m < BATCH*X3H4; m += NTHR){
                int b = m / X3H4, sl = m - b*X3H4;
                float4 v;
                if (sl >= H4 && sl < 2*H4){
                    int c = b*H4 + (sl - H4);
                    float4 p0 = ((const float4*)g_selp[0])[c];
                    float4 p1 = ((const float4*)g_selp[1])[c];
                    float4 p2 = ((const float4*)g_selp[2])[c];
                    float4 p3 = ((const float4*)g_selp[3])[c];
                    float inv = g_invden[b];
                    v.x = (p0.x+p1.x+p2.x+p3.x)*inv;
                    v.y = (p0.y+p1.y+p2.y+p3.y)*inv;
                    v.z = (p0.z+p1.z+p2.z+p3.z)*inv;
                    v.w = (p0.w+p1.w+p2.w+p3.w)*inv;
                } else v = gx4[m];
                xs4[m] = v;
            }
            __syncthreads();
        }
        for (int task = W; task < 1152; task += NW){
            int r0 = task*2;
            const float4* wiA = wih4 + (size_t)r0*X3H4;
            const float4* wiB = wiA + X3H4;
            float giA[8]={0,0,0,0,0,0,0,0}, giB[8]={0,0,0,0,0,0,0,0};
            for (int i = 0; i < 18; i++){
                float4 wa = wiA[i*32 + lane], wb = wiB[i*32 + lane];
                #pragma unroll
                for (int b = 0; b < 8; b++){
                    float4 x = xs4[b*X3H4 + i*32 + lane];
                    giA[b] += wa.x*x.x + wa.y*x.y + wa.z*x.z + wa.w*x.w;
                    giB[b] += wb.x*x.x + wb.y*x.y + wb.z*x.z + wb.w*x.w;
                }
            }
            #pragma unroll
            for (int b = 0; b < 8; b++){ giA[b] = wred(giA[b]); giB[b] = wred(giB[b]); }
            if (lane < 8){
                #pragma unroll
                for (int rr = 0; rr < 2; rr++){
                    int r = r0 + rr;
                    int g = r/H, j = r - g*H;
                    float gi = rr ? giB[0] : giA[0];
                    #pragma unroll
                    for (int b = 1; b < 8; b++)
                        if (lane == b) gi = rr ? giB[b] : giA[b];
                    float bi = bih[r];
                    if (g < 2) g_gRZ[g][lane][j] = gi + bi + g_ghv[g][lane][j];
                    else       g_gNi[lane][j]   = gi + bi;
                }
            }
        }
        gridbar(bt);

        // ===== P4: combine h; th2 (1536) + th-next (1536) + gen [0,G_P4)  (2 waves)
        {
            if (tid < 8) bmax[tid] = 0u;
            for (int m = tid; m < BATCH*H4; m += NTHR){
                int b = m/H4, c = m - b*H4;
                float4 r0 = ((const float4*)g_gRZ[0][b])[c];
                float4 r1 = ((const float4*)g_gRZ[1][b])[c];
                float4 ni = ((const float4*)g_gNi[b])[c];
                float4 nh = ((const float4*)g_ghv[2][b])[c];
                float4 ho = hs4[m];
                float4 hv;
                hv.x = gruc(r0.x, r1.x, ni.x, nh.x, ho.x);
                hv.y = gruc(r0.y, r1.y, ni.y, nh.y, ho.y);
                hv.z = gruc(r0.z, r1.z, ni.z, nh.z, ho.z);
                hv.w = gruc(r0.w, r1.w, ni.w, nh.w, ho.w);
                hs4[m] = hv;
            }
            __syncthreads();
        }
        for (int task = W; task < 4736; task += NW){
            if (task < 3072){
                int is_th = (task >= 1536);
                int tt = is_th ? task - 1536 : task;
                int bh = tt & 1, j = tt >> 1;
                int b0 = bh*4;
                const ulonglong2* r2 = (const ulonglong2*)((is_th ? aw4 : cw4) + (size_t)j*H4);
                const ulonglong2* HS = (const ulonglong2*)hs4;
                unsigned long long a0=0ull, a1=0ull, a2=0ull, a3=0ull;
                #pragma unroll
                for (int i = 0; i < 6; i++){
                    ulonglong2 w = r2[i*32 + lane];
                    ulonglong2 h0 = HS[(b0+0)*H4 + i*32 + lane];
                    ulonglong2 h1 = HS[(b0+1)*H4 + i*32 + lane];
                    ulonglong2 h2 = HS[(b0+2)*H4 + i*32 + lane];
                    ulonglong2 h3 = HS[(b0+3)*H4 + i*32 + lane];
                    a0 = ffma2(w.x, h0.x, a0); a0 = ffma2(w.y, h0.y, a0);
                    a1 = ffma2(w.x, h1.x, a1); a1 = ffma2(w.y, h1.y, a1);
                    a2 = ffma2(w.x, h2.x, a2); a2 = ffma2(w.y, h2.y, a2);
                    a3 = ffma2(w.x, h3.x, a3); a3 = ffma2(w.y, h3.y, a3);
                }
                float f0 = wred(hadd2(a0)), f1 = wred(hadd2(a1));
                float f2 = wred(hadd2(a2)), f3 = wred(hadd2(a3));
                if (!lane){
                    float bb = is_th ? ab[j] : cb[j];
                    float* dst = is_th ? g_th : g_th2;
                    dst[(b0+0)*H + j] = f0 + bb;
                    dst[(b0+1)*H + j] = f1 + bb;
                    dst[(b0+2)*H + j] = f2 + bb;
                    dst[(b0+3)*H + j] = f3 + bb;
                }
            } else {
                gen_block3(task - 3072, ow4, ob, hs4, lane, bmax);
            }
        }
        gridbar(bt);

        // ===== P5: stage th2; css (4096) + gen [G_P4, G_P4+G_P5)  (5 waves)
        {
            const float4* t4g = (const float4*)g_th2;
            for (int m = tid; m < BATCH*H4; m += NTHR) xs4[m] = t4g[m];
            __syncthreads();
        }
        for (int task = W; task < 4096 + G_P5; task += NW){
            if (task < 4096){
                int b = task >> 9, s = task & 511;
                float a = dot768_2(enc + ((size_t)b*SEQ + s)*H, xs4 + b*H4, lane);
                if (!lane) g_css[b*SEQ + s] = a;
            } else {
                gen_block3(G_P4 + (task - 4096), ow4, ob, hs4, lane, bmax);
            }
        }
        gridbar(bt);

        // ===== P6: copy-chain (128) + gen [G_P4+G_P5, GBLK3)  (1 wave); flush bmax
        for (int task = W; task < 128 + G_P6; task += NW){
            if (task < 128){
                int b = task >> 4, ch = task & 15;
                int s = ch*32 + lane;
                if (g_fo[b*SEQ + s]){
                    int tok = inputs[b*SEQ + s];
                    const int* ip = inputs + b*SEQ;
                    const float* cp = g_css + b*SEQ;
                    float sum = 0.f;
                    for (int s2 = 0; s2 < SEQ; s2++)
                        if (ip[s2] == tok) sum += cp[s2];
                    g_copyval[b*VOC + tok] = sum;
                    atomicMax(&bmax[b], okey(sum));
                }
            } else {
                gen_block3(G_P4 + G_P5 + (task - 128), ow4, ob, hs4, lane, bmax);
            }
        }
        __syncthreads();
        if (tid < 8) atomicMax(&g_amax[tid], bmax[tid]);
        gridbar(bt);

        // ===== P7: deterministic Z partials + copy-Z
        {
            float m8[8];
            #pragma unroll
            for (int b = 0; b < 8; b++) m8[b] = dekey(g_amax[b]);
            int v0 = cta*ZCH;
            int cnt = min(ZCH, VOC - v0);
            float e[8] = {0,0,0,0,0,0,0,0};
            if (tid < cnt){
                int v = v0 + tid;
                float4 a = ((const float4*)g_gen)[(size_t)v*2];
                float4 c = ((const float4*)g_gen)[(size_t)v*2 + 1];
                e[0] = __expf(a.x - m8[0]); e[1] = __expf(a.y - m8[1]);
                e[2] = __expf(a.z - m8[2]); e[3] = __expf(a.w - m8[3]);
                e[4] = __expf(c.x - m8[4]); e[5] = __expf(c.y - m8[5]);
                e[6] = __expf(c.z - m8[6]); e[7] = __expf(c.w - m8[7]);
            }
            #pragma unroll
            for (int o = 16; o; o >>= 1){
                #pragma unroll
                for (int b = 0; b < 8; b++) e[b] += __shfl_xor_sync(0xffffffffu, e[b], o);
            }
            if (!lane){
                #pragma unroll
                for (int b = 0; b < 8; b++) zred[wid][b] = e[b];
            }
            __syncthreads();
            if (wid < 8){
                float v = (lane < NWARP) ? zred[lane][wid] : 0.f;
                v = wred(v);
                if (!lane) g_Zp[cta][wid] = v;
            }
            if (cta == NCTA - 1 && wid >= 8){
                int b = wid - 8;
                float e2 = 0.f;
                for (int s = lane; s < SEQ; s += 32)
                    if (g_fo[b*SEQ + s])
                        e2 += __expf(g_copyval[b*VOC + inputs[b*SEQ + s]] - m8[b]);
                e2 = wred(e2);
                if (!lane) g_Zp[NCTA][b] = e2;
            }
        }
        gridbar(bt);

        // ===== P8: log-prob row + argmax
        {
            if (tid < 8){ msh[tid] = dekey(g_amax[tid]); bkey[tid] = 0ull; }
            if (wid < 8){
                float z = 0.f;
                for (int i = lane; i <= NCTA; i += 32) z += g_Zp[i][wid];
                z = wred(z);
                if (!lane) zinv[wid] = 1.f/z;
            }
            __syncthreads();
            int v0 = cta*ZCH;
            int cnt = min(ZCH, VOC - v0);
            if (tid < cnt){
                int v = v0 + tid;
                float4 a = ((const float4*)g_gen)[(size_t)v*2];
                float4 c = ((const float4*)g_gen)[(size_t)v*2 + 1];
                float gv[8] = {a.x, a.y, a.z, a.w, c.x, c.y, c.z, c.w};
                unsigned int vk = (unsigned int)(0x7FFFFFFF - v);
                #pragma unroll
                for (int b = 0; b < 8; b++){
                    float p = __expf(gv[b] - msh[b])*zinv[b];
                    if (g_present[b*VOC + v])
                        p += __expf(g_copyval[b*VOC + v] - msh[b])*zinv[b];
                    float lp = __logf(p + 1e-10f);
                    out[((size_t)b*TMAXX + t)*EXT + v] = lp;
                    unsigned long long key = (((unsigned long long)okey(lp)) << 32) | vk;
                    atomicMax(&bkey[b], key);
                }
            }
            __syncthreads();
            if (tid < 8) atomicMax(&g_amax2[tid], bkey[tid]);
        }
        gridbar(bt);
    }

    if (cta == 0 && tid < 8 && has_tail){
        unsigned long long key = g_amax2[tid];
        int samp = 0x7FFFFFFF - (int)(unsigned int)(key & 0xFFFFFFFFull);
        out[D1 + tid*TMAXX + (TMAXX - 1)] = (float)samp;
    }
}

// ---------------- host ----------------
extern "C" void kernel_launch(void* const* d_in, const int* in_sizes, int n_in,
                              void* d_out, int out_size){
    const float* enc    = (const float*)d_in[0];
    const int*   inputs = (const int*)  d_in[1];
    const int*   cls    = (const int*)  d_in[2];
    /* d_in[3] sep_to unused */
    const float* emb    = (const float*)d_in[4];
    const float* aw     = (const float*)d_in[5];
    const float* ab     = (const float*)d_in[6];
    const float* cw     = (const float*)d_in[7];
    const float* cb     = (const float*)d_in[8];
    const float* wih    = (const float*)d_in[9];
    const float* whh    = (const float*)d_in[10];
    const float* bih    = (const float*)d_in[11];
    const float* bhh    = (const float*)d_in[12];
    const float* ow     = (const float*)d_in[13];
    const float* ob     = (const float*)d_in[14];
    float* out = (float*)d_out;
    int has_tail = (out_size >= D1 + BATCH*TMAXX) ? 1 : 0;

    const int smemsz = (BATCH*X3H + BATCH*H)*sizeof(float);   // 96 KB
    cudaFuncSetAttribute(k_loop, cudaFuncAttributeMaxDynamicSharedMemorySize, smemsz);

    k_init<<<512, 256>>>(cls, emb, ab, inputs, out, has_tail);
    k_loop<<<NCTA, NTHR, smemsz>>>(enc, inputs, emb,
                                   (const float4*)aw, ab,
                                   (const float4*)cw, cb,
                                   (const float4*)wih, (const float4*)whh,
                                   bih, bhh,
                                   (const float4*)ow, ob,
                                   out, has_tail);
}